// round 5
// baseline (speedup 1.0000x reference)
#include <cuda_runtime.h>

#define BATCH  4
#define NPTS   8192
#define TOTAL  (BATCH * NPTS)
#define NB     1024
#define XMIN   (-5.0f)
#define XSPAN  10.0f
#define BH     (XSPAN / (float)NB)
#define INVH   ((float)NB / XSPAN)

#define QB     256      // queries per nn block
#define CWIN   768      // candidate window per block (fixed trip count)

// Scratch (__device__ globals — no allocation allowed):
__device__ float4 g_sorted[2][TOTAL];        // (x,y,z,|p|^2), bucket-sorted by x
__device__ int    g_off[2][BATCH][NB + 1];   // bucket prefix offsets
__device__ float  g_min[2][TOTAL];

__device__ __forceinline__ int bucket_of(float x) {
    int b = (int)floorf((x - XMIN) * INVH);
    return min(max(b, 0), NB - 1);
}

// One block per (array a, batch b): smem histogram -> scan -> smem-counter scatter.
__global__ __launch_bounds__(1024) void build_kernel(const float* __restrict__ p1,
                                                     const float* __restrict__ p2) {
    __shared__ int s[NB];
    __shared__ int cur[NB];

    const int a = blockIdx.x >> 2, b = blockIdx.x & 3;
    const float* __restrict__ src = (a ? p2 : p1) + b * NPTS * 3;
    const int t = threadIdx.x;

    s[t] = 0;
    __syncthreads();

    #pragma unroll
    for (int i = t; i < NPTS; i += 1024)
        atomicAdd(&s[bucket_of(src[3 * i])], 1);
    __syncthreads();

    int cnt = s[t];
    // Hillis-Steele inclusive scan over 1024
    #pragma unroll
    for (int o = 1; o < NB; o <<= 1) {
        int v = (t >= o) ? s[t - o] : 0;
        __syncthreads();
        s[t] += v;
        __syncthreads();
    }
    int excl = s[t] - cnt;
    g_off[a][b][t] = excl;
    cur[t] = excl;
    if (t == NB - 1) g_off[a][b][NB] = s[t];
    __syncthreads();

    float4* dst = &g_sorted[a][b * NPTS];
    #pragma unroll
    for (int i = t; i < NPTS; i += 1024) {
        float x = src[3 * i], y = src[3 * i + 1], z = src[3 * i + 2];
        float w = fmaf(x, x, fmaf(y, y, z * z));
        int pos = atomicAdd(&cur[bucket_of(x)], 1);
        dst[pos] = make_float4(x, y, z, w);
    }
}

// grid (NPTS/QB, BATCH, 2). Block scans a fixed 768-candidate smem window for
// all 256 of its sorted queries; bucket-edge test proves exactness, rare
// per-thread fallback expands outward from global.
__global__ __launch_bounds__(QB) void nn_kernel() {
    __shared__ float4 sc[CWIN];
    __shared__ int s_c0;

    const int dir = blockIdx.z;
    const int b   = blockIdx.y;
    const int qbase = blockIdx.x * QB;
    const int tid = threadIdx.x;

    const float4* __restrict__ qs   = &g_sorted[dir][b * NPTS] + qbase;
    const float4* __restrict__ cand = &g_sorted[dir ^ 1][b * NPTS];
    const int*    __restrict__ off  = g_off[dir ^ 1][b];

    if (tid == 0) {
        float xm = qs[QB / 2].x;
        int c0 = off[bucket_of(xm)] - CWIN / 2;
        s_c0 = max(0, min(c0, NPTS - CWIN));
    }
    __syncthreads();
    const int c0 = s_c0;

    #pragma unroll
    for (int j = tid; j < CWIN; j += QB)
        sc[j] = cand[c0 + j];
    __syncthreads();

    const float4 q = qs[tid];
    const float qx2 = -2.0f * q.x, qy2 = -2.0f * q.y, qz2 = -2.0f * q.z;
    const float qn = q.w;

    float best = 3.4e38f;            // tracks (cn - 2 q.c); +qn deferred
    #pragma unroll 8
    for (int m = 0; m < CWIN; m++) {
        const float4 c = sc[m];      // warp-uniform broadcast LDS.128
        float t = fmaf(qx2, c.x, c.w);
        t = fmaf(qy2, c.y, t);
        t = fmaf(qz2, c.z, t);
        best = fminf(best, t);
    }
    float bestd = best + qn;         // true min dist^2 over the window

    // ---- exactness check + rare fallback ----
    // Points left of window: index < c0 -> bucket <= bucket(sc[0].x) -> x <= its upper edge.
    if (c0 > 0) {
        int lb = bucket_of(sc[0].x);         // rescan of boundary bucket is harmless
        while (lb >= 0) {
            float edge = XMIN + (float)(lb + 1) * BH;
            float gap = q.x - edge;
            if (gap > 0.0f && gap * gap >= bestd) break;
            for (int i = off[lb]; i < off[lb + 1]; i++) {
                float4 c = cand[i];
                float t = fmaf(qx2, c.x, c.w);
                t = fmaf(qy2, c.y, t);
                t = fmaf(qz2, c.z, t);
                best = fminf(best, t);
            }
            bestd = best + qn;
            lb--;
        }
    }
    // Points right of window: index >= c0+CWIN -> bucket >= bucket(sc[CWIN-1].x) -> x >= its lower edge.
    if (c0 + CWIN < NPTS) {
        int rb = bucket_of(sc[CWIN - 1].x);
        while (rb < NB) {
            float edge = XMIN + (float)rb * BH;
            float gap = edge - q.x;
            if (gap > 0.0f && gap * gap >= bestd) break;
            for (int i = off[rb]; i < off[rb + 1]; i++) {
                float4 c = cand[i];
                float t = fmaf(qx2, c.x, c.w);
                t = fmaf(qy2, c.y, t);
                t = fmaf(qz2, c.z, t);
                best = fminf(best, t);
            }
            bestd = best + qn;
            rb++;
        }
    }

    g_min[dir][b * NPTS + qbase + tid] = bestd;
}

__global__ void reduce_kernel(float* __restrict__ out) {
    __shared__ float ssum[32];
    const int tid = threadIdx.x;
    const float* vals = (const float*)g_min;

    float s = 0.0f;
    for (int i = tid; i < 2 * TOTAL; i += blockDim.x)
        s += vals[i];

    #pragma unroll
    for (int o = 16; o; o >>= 1) s += __shfl_down_sync(0xffffffffu, s, o);
    if ((tid & 31) == 0) ssum[tid >> 5] = s;
    __syncthreads();
    if (tid < 32) {
        s = (tid < (int)(blockDim.x >> 5)) ? ssum[tid] : 0.0f;
        #pragma unroll
        for (int o = 16; o; o >>= 1) s += __shfl_down_sync(0xffffffffu, s, o);
        if (tid == 0) out[0] = s / (float)(BATCH * NPTS);
    }
}

extern "C" void kernel_launch(void* const* d_in, const int* in_sizes, int n_in,
                              void* d_out, int out_size) {
    const float* p1 = (const float*)d_in[0];
    const float* p2 = (const float*)d_in[1];

    build_kernel<<<2 * BATCH, 1024>>>(p1, p2);
    dim3 grid(NPTS / QB, BATCH, 2);
    nn_kernel<<<grid, QB>>>();
    reduce_kernel<<<1, 1024>>>((float*)d_out);
}

// round 6
// speedup vs baseline: 4.2430x; 4.2430x over previous
#include <cuda_runtime.h>

#define BATCH  4
#define NPTS   8192
#define TOTAL  (BATCH * NPTS)
#define NB     1024
#define XMIN   (-5.0f)
#define XSPAN  10.0f
#define BH     (XSPAN / (float)NB)
#define INVH   ((float)NB / XSPAN)

#define QB       256     // queries per nn block
#define CWIN     1024    // candidate window (smem) per block
#define NTHREADS 128     // nn block threads (each owns 2 queries)

#define FB_BLOCKS  256
#define FB_THREADS 256
#define FB_WARPS   (FB_BLOCKS * FB_THREADS / 32)

// Scratch (__device__ globals — no allocation allowed):
__device__ float4 g_sorted[2][TOTAL];       // (x,y,z,|p|^2), bucket-sorted by x
__device__ int    g_off[2][BATCH][NB + 1];  // bucket prefix offsets
__device__ float  g_min[2][TOTAL];
__device__ int    g_nfail;
__device__ int    g_fail[2 * TOTAL];        // capacity: every query

__device__ __forceinline__ int bucket_of(float x) {
    int b = (int)floorf((x - XMIN) * INVH);
    return min(max(b, 0), NB - 1);
}

// One block per (array a, batch b). Points held in registers across
// hist -> warp-shuffle scan -> scatter (single global read pass).
__global__ __launch_bounds__(1024) void build_kernel(const float* __restrict__ p1,
                                                     const float* __restrict__ p2) {
    __shared__ int s[NB];
    __shared__ int cur[NB];
    __shared__ int wsum[32];

    const int a = blockIdx.x >> 2, b = blockIdx.x & 3;
    const float* __restrict__ src = (a ? p2 : p1) + b * NPTS * 3;
    const int t = threadIdx.x;
    const int lane = t & 31, warp = t >> 5;

    float px[8], py[8], pz[8];
    int bk[8];
    #pragma unroll
    for (int j = 0; j < 8; j++) {
        int i = t + j * 1024;
        px[j] = src[3 * i];
        py[j] = src[3 * i + 1];
        pz[j] = src[3 * i + 2];
        bk[j] = bucket_of(px[j]);
    }

    s[t] = 0;
    __syncthreads();
    #pragma unroll
    for (int j = 0; j < 8; j++) atomicAdd(&s[bk[j]], 1);
    __syncthreads();

    const int cnt = s[t];
    int v = cnt;                               // inclusive scan within warp
    #pragma unroll
    for (int o = 1; o < 32; o <<= 1) {
        int u = __shfl_up_sync(0xffffffffu, v, o);
        if (lane >= o) v += u;
    }
    if (lane == 31) wsum[warp] = v;
    __syncthreads();
    if (t < 32) {
        int w = wsum[t];
        #pragma unroll
        for (int o = 1; o < 32; o <<= 1) {
            int u = __shfl_up_sync(0xffffffffu, w, o);
            if (t >= o) w += u;
        }
        wsum[t] = w;
    }
    __syncthreads();
    const int incl = v + (warp ? wsum[warp - 1] : 0);
    const int excl = incl - cnt;
    g_off[a][b][t] = excl;
    cur[t] = excl;
    if (t == NB - 1) g_off[a][b][NB] = incl;
    if (blockIdx.x == 0 && t == 0) g_nfail = 0;
    __syncthreads();

    float4* dst = &g_sorted[a][b * NPTS];
    #pragma unroll
    for (int j = 0; j < 8; j++) {
        float w = fmaf(px[j], px[j], fmaf(py[j], py[j], pz[j] * pz[j]));
        int pos = atomicAdd(&cur[bk[j]], 1);
        dst[pos] = make_float4(px[j], py[j], pz[j], w);
    }
}

// grid (NPTS/QB, BATCH, 2). Branch-free window scan; failures pushed to list.
__global__ __launch_bounds__(NTHREADS) void nn_kernel() {
    __shared__ float4 sc[CWIN];   // 16 KB
    __shared__ int s_c0;

    const int dir = blockIdx.z;
    const int b   = blockIdx.y;
    const int qbase = blockIdx.x * QB;
    const int tid = threadIdx.x;

    const float4* __restrict__ qs   = &g_sorted[dir][b * NPTS] + qbase;
    const float4* __restrict__ cand = &g_sorted[dir ^ 1][b * NPTS];
    const int*    __restrict__ off  = g_off[dir ^ 1][b];

    if (tid == 0) {
        int c0 = off[bucket_of(qs[QB / 2].x)] - CWIN / 2;
        s_c0 = max(0, min(c0, NPTS - CWIN));
    }
    __syncthreads();
    const int c0 = s_c0;

    #pragma unroll
    for (int j = tid; j < CWIN; j += NTHREADS)
        sc[j] = cand[c0 + j];
    __syncthreads();

    const float4 q0 = qs[tid];
    const float4 q1 = qs[tid + NTHREADS];
    const float ax = -2.0f * q0.x, ay = -2.0f * q0.y, az = -2.0f * q0.z;
    const float bx = -2.0f * q1.x, by = -2.0f * q1.y, bz = -2.0f * q1.z;

    float m0 = 3.4e38f, m1 = 3.4e38f;   // track (cn - 2 q.c); +qn deferred
    #pragma unroll 8
    for (int m = 0; m < CWIN; m++) {
        const float4 c = sc[m];          // warp-uniform broadcast LDS.128
        float t0 = fmaf(az, c.z, c.w);
        float t1 = fmaf(bz, c.z, c.w);
        t0 = fmaf(ay, c.y, t0);
        t1 = fmaf(by, c.y, t1);
        t0 = fmaf(ax, c.x, t0);
        t1 = fmaf(bx, c.x, t1);
        m0 = fminf(m0, t0);
        m1 = fminf(m1, t1);
    }
    const float d0 = m0 + q0.w;
    const float d1 = m1 + q1.w;

    // Safety proof: excluded left points have x <= el; excluded right have x >= er.
    const float el = XMIN + (float)(bucket_of(sc[0].x) + 1) * BH;
    const float er = XMIN + (float)bucket_of(sc[CWIN - 1].x) * BH;
    const bool lok = (c0 == 0);
    const bool rok = (c0 + CWIN >= NPTS);

    bool safe0 = (lok || (q0.x >= el && (q0.x - el) * (q0.x - el) >= d0)) &&
                 (rok || (q0.x <= er && (er - q0.x) * (er - q0.x) >= d0));
    bool safe1 = (lok || (q1.x >= el && (q1.x - el) * (q1.x - el) >= d1)) &&
                 (rok || (q1.x <= er && (er - q1.x) * (er - q1.x) >= d1));

    float* outp = &g_min[dir][b * NPTS + qbase];
    outp[tid] = d0;
    outp[tid + NTHREADS] = d1;

    if (!safe0) {
        int i = atomicAdd(&g_nfail, 1);
        g_fail[i] = dir * TOTAL + b * NPTS + qbase + tid;
    }
    if (!safe1) {
        int i = atomicAdd(&g_nfail, 1);
        g_fail[i] = dir * TOTAL + b * NPTS + qbase + tid + NTHREADS;
    }
}

// One warp per failed query: dense exact scan of all 8192 candidates.
__global__ __launch_bounds__(FB_THREADS) void fallback_kernel() {
    const int gw = (blockIdx.x * FB_THREADS + threadIdx.x) >> 5;
    const int lane = threadIdx.x & 31;
    const int nf = g_nfail;

    for (int f = gw; f < nf; f += FB_WARPS) {
        const int g = g_fail[f];
        const int dir = g / TOTAL;
        const int rem = g - dir * TOTAL;
        const int b = rem / NPTS;

        const float4 q = g_sorted[dir][rem];
        const float4* __restrict__ cand = &g_sorted[dir ^ 1][b * NPTS];
        const float ax = -2.0f * q.x, ay = -2.0f * q.y, az = -2.0f * q.z;

        float best = 3.4e38f;
        #pragma unroll 4
        for (int i = lane; i < NPTS; i += 32) {
            float4 c = cand[i];
            float t = fmaf(az, c.z, c.w);
            t = fmaf(ay, c.y, t);
            t = fmaf(ax, c.x, t);
            best = fminf(best, t);
        }
        #pragma unroll
        for (int o = 16; o; o >>= 1)
            best = fminf(best, __shfl_xor_sync(0xffffffffu, best, o));
        if (lane == 0) g_min[dir][rem] = best + q.w;
    }
}

__global__ void reduce_kernel(float* __restrict__ out) {
    __shared__ float ssum[32];
    const int tid = threadIdx.x;
    const float* vals = (const float*)g_min;

    float s = 0.0f;
    for (int i = tid; i < 2 * TOTAL; i += blockDim.x)
        s += vals[i];

    #pragma unroll
    for (int o = 16; o; o >>= 1) s += __shfl_down_sync(0xffffffffu, s, o);
    if ((tid & 31) == 0) ssum[tid >> 5] = s;
    __syncthreads();
    if (tid < 32) {
        s = (tid < (int)(blockDim.x >> 5)) ? ssum[tid] : 0.0f;
        #pragma unroll
        for (int o = 16; o; o >>= 1) s += __shfl_down_sync(0xffffffffu, s, o);
        if (tid == 0) out[0] = s / (float)(BATCH * NPTS);
    }
}

extern "C" void kernel_launch(void* const* d_in, const int* in_sizes, int n_in,
                              void* d_out, int out_size) {
    const float* p1 = (const float*)d_in[0];
    const float* p2 = (const float*)d_in[1];

    build_kernel<<<2 * BATCH, 1024>>>(p1, p2);
    dim3 grid(NPTS / QB, BATCH, 2);
    nn_kernel<<<grid, NTHREADS>>>();
    fallback_kernel<<<FB_BLOCKS, FB_THREADS>>>();
    reduce_kernel<<<1, 1024>>>((float*)d_out);
}

// round 7
// speedup vs baseline: 6.9174x; 1.6303x over previous
#include <cuda_runtime.h>

#define BATCH  4
#define NPTS   8192
#define TOTAL  (BATCH * NPTS)
#define NB     1024
#define XMIN   (-5.0f)
#define BH     (10.0f / (float)NB)
#define INVH   ((float)NB / 10.0f)

#define QB       256     // queries per nn block
#define CWIN     2048    // candidate window (smem) per block
#define NTHREADS 128     // nn threads (2 queries per thread)

#define FB_BLOCKS  256
#define FB_THREADS 256
#define FB_WARPS   (FB_BLOCKS * FB_THREADS / 32)

#define SCALE (1.0f / (float)TOTAL)

// Scratch (__device__ globals — no allocation allowed):
__device__ float4 g_sorted[2][TOTAL];       // (x,y,z,|p|^2), bucket-sorted by x
__device__ int    g_off[2][BATCH][NB + 1];
__device__ float  g_best[2][TOTAL];         // window-exact upper bound per query
__device__ int    g_nfail;
__device__ int    g_fail[2 * TOTAL];

__device__ __forceinline__ int bucket_of(float x) {
    int b = (int)floorf((x - XMIN) * INVH);
    return min(max(b, 0), NB - 1);
}

// One block per (array a, batch b): regs -> smem hist -> shuffle scan -> scatter.
__global__ __launch_bounds__(1024) void build_kernel(const float* __restrict__ p1,
                                                     const float* __restrict__ p2,
                                                     float* __restrict__ out) {
    __shared__ int s[NB];
    __shared__ int cur[NB];
    __shared__ int wsum[32];

    const int a = blockIdx.x >> 2, b = blockIdx.x & 3;
    const float* __restrict__ src = (a ? p2 : p1) + b * NPTS * 3;
    const int t = threadIdx.x;
    const int lane = t & 31, warp = t >> 5;

    float px[8], py[8], pz[8];
    int bk[8];
    #pragma unroll
    for (int j = 0; j < 8; j++) {
        int i = t + j * 1024;
        px[j] = src[3 * i];
        py[j] = src[3 * i + 1];
        pz[j] = src[3 * i + 2];
        bk[j] = bucket_of(px[j]);
    }

    s[t] = 0;
    __syncthreads();
    #pragma unroll
    for (int j = 0; j < 8; j++) atomicAdd(&s[bk[j]], 1);
    __syncthreads();

    const int cnt = s[t];
    int v = cnt;
    #pragma unroll
    for (int o = 1; o < 32; o <<= 1) {
        int u = __shfl_up_sync(0xffffffffu, v, o);
        if (lane >= o) v += u;
    }
    if (lane == 31) wsum[warp] = v;
    __syncthreads();
    if (t < 32) {
        int w = wsum[t];
        #pragma unroll
        for (int o = 1; o < 32; o <<= 1) {
            int u = __shfl_up_sync(0xffffffffu, w, o);
            if (t >= o) w += u;
        }
        wsum[t] = w;
    }
    __syncthreads();
    const int incl = v + (warp ? wsum[warp - 1] : 0);
    const int excl = incl - cnt;
    g_off[a][b][t] = excl;
    cur[t] = excl;
    if (t == NB - 1) g_off[a][b][NB] = incl;
    if (blockIdx.x == 0 && t == 0) { g_nfail = 0; out[0] = 0.0f; }
    __syncthreads();

    float4* dst = &g_sorted[a][b * NPTS];
    #pragma unroll
    for (int j = 0; j < 8; j++) {
        float w = fmaf(px[j], px[j], fmaf(py[j], py[j], pz[j] * pz[j]));
        int pos = atomicAdd(&cur[bk[j]], 1);
        dst[pos] = make_float4(px[j], py[j], pz[j], w);
    }
}

// grid (NPTS/QB, BATCH, 2). Window scan; safe results summed in-block,
// unsafe pushed to fail list with their exact-over-window bound.
__global__ __launch_bounds__(NTHREADS) void nn_kernel(float* __restrict__ out) {
    __shared__ float4 sc[CWIN];    // 32 KB
    __shared__ int s_c0;
    __shared__ float spart[NTHREADS / 32];

    const int dir = blockIdx.z;
    const int b   = blockIdx.y;
    const int qbase = blockIdx.x * QB;
    const int tid = threadIdx.x;
    const int lane = tid & 31, warp = tid >> 5;

    const float4* __restrict__ qs   = &g_sorted[dir][b * NPTS] + qbase;
    const float4* __restrict__ cand = &g_sorted[dir ^ 1][b * NPTS];
    const int*    __restrict__ off  = g_off[dir ^ 1][b];

    if (tid == 0) {
        int c0 = off[bucket_of(qs[QB / 2].x)] - CWIN / 2;
        s_c0 = max(0, min(c0, NPTS - CWIN));
    }
    __syncthreads();
    const int c0 = s_c0;

    #pragma unroll
    for (int j = tid; j < CWIN; j += NTHREADS)
        sc[j] = cand[c0 + j];
    __syncthreads();

    const float4 q0 = qs[tid];
    const float4 q1 = qs[tid + NTHREADS];
    const float ax = -2.0f * q0.x, ay = -2.0f * q0.y, az = -2.0f * q0.z;
    const float bx = -2.0f * q1.x, by = -2.0f * q1.y, bz = -2.0f * q1.z;

    float m0 = 3.4e38f, m1 = 3.4e38f;    // (cn - 2 q.c); +qn deferred
    #pragma unroll 8
    for (int m = 0; m < CWIN; m++) {
        const float4 c = sc[m];           // warp-uniform broadcast LDS.128
        float t0 = fmaf(az, c.z, c.w);
        float t1 = fmaf(bz, c.z, c.w);
        t0 = fmaf(ay, c.y, t0);
        t1 = fmaf(by, c.y, t1);
        t0 = fmaf(ax, c.x, t0);
        t1 = fmaf(bx, c.x, t1);
        m0 = fminf(m0, t0);
        m1 = fminf(m1, t1);
    }
    const float d0 = m0 + q0.w;
    const float d1 = m1 + q1.w;

    // Excluded left points: x <= el; excluded right: x >= er.
    const float el = XMIN + (float)(bucket_of(sc[0].x) + 1) * BH;
    const float er = XMIN + (float)bucket_of(sc[CWIN - 1].x) * BH;
    const bool lok = (c0 == 0);
    const bool rok = (c0 + CWIN >= NPTS);

    const bool safe0 = (lok || (q0.x >= el && (q0.x - el) * (q0.x - el) >= d0)) &&
                       (rok || (q0.x <= er && (er - q0.x) * (er - q0.x) >= d0));
    const bool safe1 = (lok || (q1.x >= el && (q1.x - el) * (q1.x - el) >= d1)) &&
                       (rok || (q1.x <= er && (er - q1.x) * (er - q1.x) >= d1));

    if (!safe0) {
        g_best[dir][b * NPTS + qbase + tid] = d0;
        g_fail[atomicAdd(&g_nfail, 1)] = dir * TOTAL + b * NPTS + qbase + tid;
    }
    if (!safe1) {
        g_best[dir][b * NPTS + qbase + tid + NTHREADS] = d1;
        g_fail[atomicAdd(&g_nfail, 1)] = dir * TOTAL + b * NPTS + qbase + tid + NTHREADS;
    }

    // Block-sum of safe contributions only.
    float contrib = (safe0 ? d0 : 0.0f) + (safe1 ? d1 : 0.0f);
    #pragma unroll
    for (int o = 16; o; o >>= 1) contrib += __shfl_down_sync(0xffffffffu, contrib, o);
    if (lane == 0) spart[warp] = contrib;
    __syncthreads();
    if (tid == 0) {
        float tot = 0.0f;
        #pragma unroll
        for (int w = 0; w < NTHREADS / 32; w++) tot += spart[w];
        atomicAdd(out, tot * SCALE);
    }
}

// One warp per failed query: scan only the contiguous index range that can
// beat the window bound (|dx| < sqrt(bestd)); add final value to the sum.
__global__ __launch_bounds__(FB_THREADS) void fallback_kernel(float* __restrict__ out) {
    const int gw = (blockIdx.x * FB_THREADS + threadIdx.x) >> 5;
    const int lane = threadIdx.x & 31;
    const int nf = g_nfail;

    float acc = 0.0f;
    for (int f = gw; f < nf; f += FB_WARPS) {
        const int g = g_fail[f];
        const int dir = g / TOTAL;
        const int rem = g - dir * TOTAL;
        const int b = rem / NPTS;

        const float4 q = g_sorted[dir][rem];
        const float bestd = g_best[dir][rem];
        const float4* __restrict__ cand = &g_sorted[dir ^ 1][b * NPTS];
        const int* __restrict__ off = g_off[dir ^ 1][b];

        const float s = sqrtf(bestd);
        const int lo = off[bucket_of(q.x - s)];
        const int hi = off[bucket_of(q.x + s) + 1];

        const float ax = -2.0f * q.x, ay = -2.0f * q.y, az = -2.0f * q.z;
        float best = bestd - q.w;
        for (int i = lo + lane; i < hi; i += 32) {
            float4 c = cand[i];
            float t = fmaf(az, c.z, c.w);
            t = fmaf(ay, c.y, t);
            t = fmaf(ax, c.x, t);
            best = fminf(best, t);
        }
        #pragma unroll
        for (int o = 16; o; o >>= 1)
            best = fminf(best, __shfl_xor_sync(0xffffffffu, best, o));
        if (lane == 0) acc += best + q.w;
    }
    if (acc != 0.0f) atomicAdd(out, acc * SCALE);
}

extern "C" void kernel_launch(void* const* d_in, const int* in_sizes, int n_in,
                              void* d_out, int out_size) {
    const float* p1 = (const float*)d_in[0];
    const float* p2 = (const float*)d_in[1];
    float* out = (float*)d_out;

    build_kernel<<<2 * BATCH, 1024>>>(p1, p2, out);
    dim3 grid(NPTS / QB, BATCH, 2);
    nn_kernel<<<grid, NTHREADS>>>(out);
    fallback_kernel<<<FB_BLOCKS, FB_THREADS>>>(out);
}

// round 8
// speedup vs baseline: 7.7692x; 1.1231x over previous
#include <cuda_runtime.h>

#define BATCH  4
#define NPTS   8192
#define TOTAL  (BATCH * NPTS)
#define NB     1024
#define XMIN   (-5.0f)
#define BH     (10.0f / (float)NB)
#define INVH   ((float)NB / 10.0f)

#define QB       256     // queries per nn block
#define CWIN     1536    // candidate window (smem) per block
#define NTHREADS 128     // nn threads (2 queries per thread)

#define FB_BLOCKS  256
#define FB_THREADS 256
#define FB_WARPS   (FB_BLOCKS * FB_THREADS / 32)

#define SCALE (1.0f / (float)TOTAL)

// Scratch (__device__ globals — no allocation allowed):
__device__ float4 g_sorted[2][TOTAL];       // (x,y,z,|p|^2), bucket-sorted by x
__device__ int    g_hist[2][BATCH][NB];
__device__ int    g_off[2][BATCH][NB + 1];
__device__ int    g_cur[2][BATCH][NB];
__device__ float  g_best[2][TOTAL];         // window bound for failed queries
__device__ int    g_nfail;
__device__ int    g_fail[2 * TOTAL];

__device__ __forceinline__ int bucket_of(float x) {
    int b = (int)floorf((x - XMIN) * INVH);
    return min(max(b, 0), NB - 1);
}

__global__ void zero_kernel(float* __restrict__ out) {
    int i = blockIdx.x * blockDim.x + threadIdx.x;
    if (i < 2 * BATCH * NB) ((int*)g_hist)[i] = 0;
    if (i == 0) { g_nfail = 0; out[0] = 0.0f; }
}

// grid (8 segments, 8 array-batch pairs) x 1024: spread global atomics.
__global__ __launch_bounds__(1024) void hist_kernel(const float* __restrict__ p1,
                                                    const float* __restrict__ p2) {
    const int ab = blockIdx.y;
    const int a = ab >> 2, b = ab & 3;
    const float* __restrict__ src = (a ? p2 : p1) + b * NPTS * 3;
    const int i = blockIdx.x * 1024 + threadIdx.x;
    atomicAdd(&g_hist[a][b][bucket_of(src[3 * i])], 1);
}

// One block per (a,b): warp-shuffle scan of the 1024-bucket histogram.
__global__ __launch_bounds__(1024) void scan_kernel() {
    __shared__ int wsum[32];
    const int a = blockIdx.x >> 2, b = blockIdx.x & 3;
    const int t = threadIdx.x;
    const int lane = t & 31, warp = t >> 5;

    const int cnt = g_hist[a][b][t];
    int v = cnt;
    #pragma unroll
    for (int o = 1; o < 32; o <<= 1) {
        int u = __shfl_up_sync(0xffffffffu, v, o);
        if (lane >= o) v += u;
    }
    if (lane == 31) wsum[warp] = v;
    __syncthreads();
    if (t < 32) {
        int w = wsum[t];
        #pragma unroll
        for (int o = 1; o < 32; o <<= 1) {
            int u = __shfl_up_sync(0xffffffffu, w, o);
            if (t >= o) w += u;
        }
        wsum[t] = w;
    }
    __syncthreads();
    const int incl = v + (warp ? wsum[warp - 1] : 0);
    const int excl = incl - cnt;
    g_off[a][b][t] = excl;
    g_cur[a][b][t] = excl;
    if (t == NB - 1) g_off[a][b][NB] = incl;
}

// grid (8 segments, 8 pairs) x 1024: spread global atomics for positions.
__global__ __launch_bounds__(1024) void scatter_kernel(const float* __restrict__ p1,
                                                       const float* __restrict__ p2) {
    const int ab = blockIdx.y;
    const int a = ab >> 2, b = ab & 3;
    const float* __restrict__ src = (a ? p2 : p1) + b * NPTS * 3;
    const int i = blockIdx.x * 1024 + threadIdx.x;

    float x = src[3 * i], y = src[3 * i + 1], z = src[3 * i + 2];
    float w = fmaf(x, x, fmaf(y, y, z * z));
    int pos = atomicAdd(&g_cur[a][b][bucket_of(x)], 1);
    g_sorted[a][b * NPTS + pos] = make_float4(x, y, z, w);
}

// grid (NPTS/QB, BATCH, 2). Window scan; safe results summed in-block,
// unsafe pushed to fail list with their exact-over-window bound.
__global__ __launch_bounds__(NTHREADS) void nn_kernel(float* __restrict__ out) {
    __shared__ float4 sc[CWIN];    // 24 KB
    __shared__ int s_c0;
    __shared__ float spart[NTHREADS / 32];

    const int dir = blockIdx.z;
    const int b   = blockIdx.y;
    const int qbase = blockIdx.x * QB;
    const int tid = threadIdx.x;
    const int lane = tid & 31, warp = tid >> 5;

    const float4* __restrict__ qs   = &g_sorted[dir][b * NPTS] + qbase;
    const float4* __restrict__ cand = &g_sorted[dir ^ 1][b * NPTS];
    const int*    __restrict__ off  = g_off[dir ^ 1][b];

    if (tid == 0) {
        int c0 = off[bucket_of(qs[QB / 2].x)] - CWIN / 2;
        s_c0 = max(0, min(c0, NPTS - CWIN));
    }
    __syncthreads();
    const int c0 = s_c0;

    #pragma unroll
    for (int j = tid; j < CWIN; j += NTHREADS)
        sc[j] = cand[c0 + j];
    __syncthreads();

    const float4 q0 = qs[tid];
    const float4 q1 = qs[tid + NTHREADS];
    const float ax = -2.0f * q0.x, ay = -2.0f * q0.y, az = -2.0f * q0.z;
    const float bx = -2.0f * q1.x, by = -2.0f * q1.y, bz = -2.0f * q1.z;

    float m0 = 3.4e38f, m1 = 3.4e38f;    // (cn - 2 q.c); +qn deferred
    #pragma unroll 8
    for (int m = 0; m < CWIN; m++) {
        const float4 c = sc[m];           // warp-uniform broadcast LDS.128
        float t0 = fmaf(az, c.z, c.w);
        float t1 = fmaf(bz, c.z, c.w);
        t0 = fmaf(ay, c.y, t0);
        t1 = fmaf(by, c.y, t1);
        t0 = fmaf(ax, c.x, t0);
        t1 = fmaf(bx, c.x, t1);
        m0 = fminf(m0, t0);
        m1 = fminf(m1, t1);
    }
    const float d0 = m0 + q0.w;
    const float d1 = m1 + q1.w;

    // Excluded left points: x <= el; excluded right: x >= er.
    const float el = XMIN + (float)(bucket_of(sc[0].x) + 1) * BH;
    const float er = XMIN + (float)bucket_of(sc[CWIN - 1].x) * BH;
    const bool lok = (c0 == 0);
    const bool rok = (c0 + CWIN >= NPTS);

    const bool safe0 = (lok || (q0.x >= el && (q0.x - el) * (q0.x - el) >= d0)) &&
                       (rok || (q0.x <= er && (er - q0.x) * (er - q0.x) >= d0));
    const bool safe1 = (lok || (q1.x >= el && (q1.x - el) * (q1.x - el) >= d1)) &&
                       (rok || (q1.x <= er && (er - q1.x) * (er - q1.x) >= d1));

    if (!safe0) {
        g_best[dir][b * NPTS + qbase + tid] = d0;
        g_fail[atomicAdd(&g_nfail, 1)] = dir * TOTAL + b * NPTS + qbase + tid;
    }
    if (!safe1) {
        g_best[dir][b * NPTS + qbase + tid + NTHREADS] = d1;
        g_fail[atomicAdd(&g_nfail, 1)] = dir * TOTAL + b * NPTS + qbase + tid + NTHREADS;
    }

    float contrib = (safe0 ? d0 : 0.0f) + (safe1 ? d1 : 0.0f);
    #pragma unroll
    for (int o = 16; o; o >>= 1) contrib += __shfl_down_sync(0xffffffffu, contrib, o);
    if (lane == 0) spart[warp] = contrib;
    __syncthreads();
    if (tid == 0) {
        float tot = 0.0f;
        #pragma unroll
        for (int w = 0; w < NTHREADS / 32; w++) tot += spart[w];
        atomicAdd(out, tot * SCALE);
    }
}

// One warp per failed query: scan only the contiguous range that can beat
// the window bound (|dx| < sqrt(bestd)); add final value to the sum.
__global__ __launch_bounds__(FB_THREADS) void fallback_kernel(float* __restrict__ out) {
    const int gw = (blockIdx.x * FB_THREADS + threadIdx.x) >> 5;
    const int lane = threadIdx.x & 31;
    const int nf = g_nfail;

    float acc = 0.0f;
    for (int f = gw; f < nf; f += FB_WARPS) {
        const int g = g_fail[f];
        const int dir = g / TOTAL;
        const int rem = g - dir * TOTAL;
        const int b = rem / NPTS;

        const float4 q = g_sorted[dir][rem];
        const float bestd = g_best[dir][rem];
        const float4* __restrict__ cand = &g_sorted[dir ^ 1][b * NPTS];
        const int* __restrict__ off = g_off[dir ^ 1][b];

        const float s = sqrtf(bestd);
        const int lo = off[bucket_of(q.x - s)];
        const int hi = off[bucket_of(q.x + s) + 1];

        const float ax = -2.0f * q.x, ay = -2.0f * q.y, az = -2.0f * q.z;
        float best = bestd - q.w;
        for (int i = lo + lane; i < hi; i += 32) {
            float4 c = cand[i];
            float t = fmaf(az, c.z, c.w);
            t = fmaf(ay, c.y, t);
            t = fmaf(ax, c.x, t);
            best = fminf(best, t);
        }
        #pragma unroll
        for (int o = 16; o; o >>= 1)
            best = fminf(best, __shfl_xor_sync(0xffffffffu, best, o));
        if (lane == 0) acc += best + q.w;
    }
    if (acc != 0.0f) atomicAdd(out, acc * SCALE);
}

extern "C" void kernel_launch(void* const* d_in, const int* in_sizes, int n_in,
                              void* d_out, int out_size) {
    const float* p1 = (const float*)d_in[0];
    const float* p2 = (const float*)d_in[1];
    float* out = (float*)d_out;

    zero_kernel<<<(2 * BATCH * NB + 1023) / 1024, 1024>>>(out);
    dim3 bgrid(NPTS / 1024, 2 * BATCH);
    hist_kernel<<<bgrid, 1024>>>(p1, p2);
    scan_kernel<<<2 * BATCH, 1024>>>();
    scatter_kernel<<<bgrid, 1024>>>(p1, p2);
    dim3 ngrid(NPTS / QB, BATCH, 2);
    nn_kernel<<<ngrid, NTHREADS>>>(out);
    fallback_kernel<<<FB_BLOCKS, FB_THREADS>>>(out);
}

// round 9
// speedup vs baseline: 8.0532x; 1.0366x over previous
#include <cuda_runtime.h>

#define BATCH  4
#define NPTS   8192
#define TOTAL  (BATCH * NPTS)
#define NB     1024
#define NSEG   8                  // segments per (array,batch), 1024 pts each
#define XMIN   (-5.0f)
#define BH     (10.0f / (float)NB)
#define INVH   ((float)NB / 10.0f)

#define QB       256     // queries per nn block
#define CWIN     1280    // candidate window (smem) per block
#define NTHREADS 128     // nn threads (2 queries per thread)

#define FB_BLOCKS  256
#define FB_THREADS 256
#define FB_WARPS   (FB_BLOCKS * FB_THREADS / 32)

#define SCALE (1.0f / (float)TOTAL)

// Scratch (__device__ globals — no allocation allowed):
__device__ float4 g_sorted[2][TOTAL];          // (x,y,z,|p|^2), bucket-sorted by x
__device__ int    g_seghist[8][NSEG][NB];      // per-(ab, segment) bucket counts
__device__ int    g_segbase[8][NSEG][NB];      // scatter base per (ab, segment, bucket)
__device__ int    g_off[2][BATCH][NB + 1];     // bucket prefix offsets
__device__ float  g_best[2][TOTAL];            // window bound for failed queries
__device__ int    g_nfail;
__device__ int    g_fail[2 * TOTAL];

__device__ __forceinline__ int bucket_of(float x) {
    int b = (int)floorf((x - XMIN) * INVH);
    return min(max(b, 0), NB - 1);
}

// grid (NSEG, 8 ab-pairs) x 1024: smem histogram per segment, no global atomics.
__global__ __launch_bounds__(1024) void hist_kernel(const float* __restrict__ p1,
                                                    const float* __restrict__ p2) {
    __shared__ int s[NB];
    const int ab = blockIdx.y;
    const int a = ab >> 2, b = ab & 3;
    const float* __restrict__ src = (a ? p2 : p1) + (b * NPTS + blockIdx.x * 1024) * 3;
    const int t = threadIdx.x;

    s[t] = 0;
    __syncthreads();
    atomicAdd(&s[bucket_of(src[3 * t])], 1);
    __syncthreads();
    g_seghist[ab][blockIdx.x][t] = s[t];
}

// One block per ab: per-bucket totals across segments -> block scan -> segment bases.
__global__ __launch_bounds__(1024) void scan_kernel(float* __restrict__ out) {
    __shared__ int wsum[32];
    const int ab = blockIdx.x;
    const int a = ab >> 2, b = ab & 3;
    const int t = threadIdx.x;
    const int lane = t & 31, warp = t >> 5;

    int segc[NSEG];
    int cnt = 0;
    #pragma unroll
    for (int s = 0; s < NSEG; s++) {
        segc[s] = g_seghist[ab][s][t];
        cnt += segc[s];
    }

    int v = cnt;
    #pragma unroll
    for (int o = 1; o < 32; o <<= 1) {
        int u = __shfl_up_sync(0xffffffffu, v, o);
        if (lane >= o) v += u;
    }
    if (lane == 31) wsum[warp] = v;
    __syncthreads();
    if (t < 32) {
        int w = wsum[t];
        #pragma unroll
        for (int o = 1; o < 32; o <<= 1) {
            int u = __shfl_up_sync(0xffffffffu, w, o);
            if (t >= o) w += u;
        }
        wsum[t] = w;
    }
    __syncthreads();
    const int incl = v + (warp ? wsum[warp - 1] : 0);
    int base = incl - cnt;                 // exclusive bucket base
    g_off[a][b][t] = base;
    if (t == NB - 1) g_off[a][b][NB] = incl;
    if (ab == 0 && t == 0) { g_nfail = 0; out[0] = 0.0f; }

    #pragma unroll
    for (int s = 0; s < NSEG; s++) {
        g_segbase[ab][s][t] = base;
        base += segc[s];
    }
}

// grid (NSEG, 8 ab) x 1024: rank via smem atomics over precomputed segment bases.
__global__ __launch_bounds__(1024) void scatter_kernel(const float* __restrict__ p1,
                                                       const float* __restrict__ p2) {
    __shared__ int cur[NB];
    const int ab = blockIdx.y;
    const int a = ab >> 2, b = ab & 3;
    const float* __restrict__ src = (a ? p2 : p1) + (b * NPTS + blockIdx.x * 1024) * 3;
    const int t = threadIdx.x;

    cur[t] = g_segbase[ab][blockIdx.x][t];
    __syncthreads();

    float x = src[3 * t], y = src[3 * t + 1], z = src[3 * t + 2];
    float w = fmaf(x, x, fmaf(y, y, z * z));
    int pos = atomicAdd(&cur[bucket_of(x)], 1);
    g_sorted[a][b * NPTS + pos] = make_float4(x, y, z, w);
}

// grid (NPTS/QB, BATCH, 2). Window scan; safe results summed in-block,
// unsafe pushed to fail list with their exact-over-window bound.
__global__ __launch_bounds__(NTHREADS) void nn_kernel(float* __restrict__ out) {
    __shared__ float4 sc[CWIN];    // 20 KB
    __shared__ int s_c0;
    __shared__ float spart[NTHREADS / 32];

    const int dir = blockIdx.z;
    const int b   = blockIdx.y;
    const int qbase = blockIdx.x * QB;
    const int tid = threadIdx.x;
    const int lane = tid & 31, warp = tid >> 5;

    const float4* __restrict__ qs   = &g_sorted[dir][b * NPTS] + qbase;
    const float4* __restrict__ cand = &g_sorted[dir ^ 1][b * NPTS];
    const int*    __restrict__ off  = g_off[dir ^ 1][b];

    if (tid == 0) {
        int c0 = off[bucket_of(qs[QB / 2].x)] - CWIN / 2;
        s_c0 = max(0, min(c0, NPTS - CWIN));
    }
    __syncthreads();
    const int c0 = s_c0;

    #pragma unroll
    for (int j = tid; j < CWIN; j += NTHREADS)
        sc[j] = cand[c0 + j];
    __syncthreads();

    const float4 q0 = qs[tid];
    const float4 q1 = qs[tid + NTHREADS];
    const float ax = -2.0f * q0.x, ay = -2.0f * q0.y, az = -2.0f * q0.z;
    const float bx = -2.0f * q1.x, by = -2.0f * q1.y, bz = -2.0f * q1.z;

    float m0 = 3.4e38f, m1 = 3.4e38f;    // (cn - 2 q.c); +qn deferred
    #pragma unroll 8
    for (int m = 0; m < CWIN; m++) {
        const float4 c = sc[m];           // warp-uniform broadcast LDS.128
        float t0 = fmaf(az, c.z, c.w);
        float t1 = fmaf(bz, c.z, c.w);
        t0 = fmaf(ay, c.y, t0);
        t1 = fmaf(by, c.y, t1);
        t0 = fmaf(ax, c.x, t0);
        t1 = fmaf(bx, c.x, t1);
        m0 = fminf(m0, t0);
        m1 = fminf(m1, t1);
    }
    const float d0 = m0 + q0.w;
    const float d1 = m1 + q1.w;

    // Excluded left points: x <= el; excluded right: x >= er.
    const float el = XMIN + (float)(bucket_of(sc[0].x) + 1) * BH;
    const float er = XMIN + (float)bucket_of(sc[CWIN - 1].x) * BH;
    const bool lok = (c0 == 0);
    const bool rok = (c0 + CWIN >= NPTS);

    const bool safe0 = (lok || (q0.x >= el && (q0.x - el) * (q0.x - el) >= d0)) &&
                       (rok || (q0.x <= er && (er - q0.x) * (er - q0.x) >= d0));
    const bool safe1 = (lok || (q1.x >= el && (q1.x - el) * (q1.x - el) >= d1)) &&
                       (rok || (q1.x <= er && (er - q1.x) * (er - q1.x) >= d1));

    if (!safe0) {
        g_best[dir][b * NPTS + qbase + tid] = d0;
        g_fail[atomicAdd(&g_nfail, 1)] = dir * TOTAL + b * NPTS + qbase + tid;
    }
    if (!safe1) {
        g_best[dir][b * NPTS + qbase + tid + NTHREADS] = d1;
        g_fail[atomicAdd(&g_nfail, 1)] = dir * TOTAL + b * NPTS + qbase + tid + NTHREADS;
    }

    float contrib = (safe0 ? d0 : 0.0f) + (safe1 ? d1 : 0.0f);
    #pragma unroll
    for (int o = 16; o; o >>= 1) contrib += __shfl_down_sync(0xffffffffu, contrib, o);
    if (lane == 0) spart[warp] = contrib;
    __syncthreads();
    if (tid == 0) {
        float tot = 0.0f;
        #pragma unroll
        for (int w = 0; w < NTHREADS / 32; w++) tot += spart[w];
        atomicAdd(out, tot * SCALE);
    }
}

// One warp per failed query: scan only the contiguous range that can beat
// the window bound (|dx| < sqrt(bestd)); add final value to the sum.
__global__ __launch_bounds__(FB_THREADS) void fallback_kernel(float* __restrict__ out) {
    const int gw = (blockIdx.x * FB_THREADS + threadIdx.x) >> 5;
    const int lane = threadIdx.x & 31;
    const int nf = g_nfail;

    float acc = 0.0f;
    for (int f = gw; f < nf; f += FB_WARPS) {
        const int g = g_fail[f];
        const int dir = g / TOTAL;
        const int rem = g - dir * TOTAL;
        const int b = rem / NPTS;

        const float4 q = g_sorted[dir][rem];
        const float bestd = g_best[dir][rem];
        const float4* __restrict__ cand = &g_sorted[dir ^ 1][b * NPTS];
        const int* __restrict__ off = g_off[dir ^ 1][b];

        const float s = sqrtf(bestd);
        const int lo = off[bucket_of(q.x - s)];
        const int hi = off[bucket_of(q.x + s) + 1];

        const float ax = -2.0f * q.x, ay = -2.0f * q.y, az = -2.0f * q.z;
        float best = bestd - q.w;
        for (int i = lo + lane; i < hi; i += 32) {
            float4 c = cand[i];
            float t = fmaf(az, c.z, c.w);
            t = fmaf(ay, c.y, t);
            t = fmaf(ax, c.x, t);
            best = fminf(best, t);
        }
        #pragma unroll
        for (int o = 16; o; o >>= 1)
            best = fminf(best, __shfl_xor_sync(0xffffffffu, best, o));
        if (lane == 0) acc += best + q.w;
    }
    if (acc != 0.0f) atomicAdd(out, acc * SCALE);
}

extern "C" void kernel_launch(void* const* d_in, const int* in_sizes, int n_in,
                              void* d_out, int out_size) {
    const float* p1 = (const float*)d_in[0];
    const float* p2 = (const float*)d_in[1];
    float* out = (float*)d_out;

    dim3 bgrid(NSEG, 2 * BATCH);
    hist_kernel<<<bgrid, 1024>>>(p1, p2);
    scan_kernel<<<2 * BATCH, 1024>>>(out);
    scatter_kernel<<<bgrid, 1024>>>(p1, p2);
    dim3 ngrid(NPTS / QB, BATCH, 2);
    nn_kernel<<<ngrid, NTHREADS>>>(out);
    fallback_kernel<<<FB_BLOCKS, FB_THREADS>>>(out);
}